// round 7
// baseline (speedup 1.0000x reference)
#include <cuda_runtime.h>
#include <cuda_bf16.h>
#include <math.h>
#include <float.h>

#define NROWS 65536      // 32*32*64
#define DIM   64
#define NE    1024
#define LDE   65         // vq_pairs tile ld

// Output layout (float32, return-order flatten)
#define ZQ_OFF   1
#define PERP_OFF (1 + NROWS*DIM)
#define IDX_OFF  (2 + NROWS*DIM)

#define DELTA 4e-5f      // ambiguity margin (> 2*approx_err + quantization window)
#define LDA   136        // padded split-row ld in bf16 (272B = 17*16B)
#define MROWS 256        // rows per filter CTA

// ---- scratch (no allocations allowed) ----
__device__ float  g_counts[NE];
__device__ float  g_en[NE];
__device__ float  g_zsq[NROWS];
__device__ int    g_amb_rows[NROWS];
__device__ int    g_amb_cnt;
__device__ double g_mse;
__device__ double g_edist;
__device__ __nv_bfloat16 g_esplit[NE * 128];       // [code][ eh(64) | el(64) ]

// ============================================================
// PTX helpers (fragment layouts validated bitwise R5/R6)
// ============================================================
__device__ __forceinline__ void ldmx4(unsigned* r, unsigned addr) {
    asm volatile("ldmatrix.sync.aligned.m8n8.x4.shared.b16 {%0,%1,%2,%3}, [%4];"
                 : "=r"(r[0]), "=r"(r[1]), "=r"(r[2]), "=r"(r[3]) : "r"(addr));
}
__device__ __forceinline__ void mma16816(float* c, const unsigned* a, const unsigned* b) {
    asm volatile("mma.sync.aligned.m16n8k16.row.col.f32.bf16.bf16.f32 "
                 "{%0,%1,%2,%3}, {%4,%5,%6,%7}, {%8,%9}, {%0,%1,%2,%3};"
                 : "+f"(c[0]), "+f"(c[1]), "+f"(c[2]), "+f"(c[3])
                 : "r"(a[0]), "r"(a[1]), "r"(a[2]), "r"(a[3]), "r"(b[0]), "r"(b[1]));
}
__device__ __forceinline__ unsigned pack_bf16_split_h(float x, float y) {
    __nv_bfloat16 hx = __float2bfloat16(x), hy = __float2bfloat16(y);
    return (unsigned)__bfloat16_as_ushort(hx) | ((unsigned)__bfloat16_as_ushort(hy) << 16);
}
__device__ __forceinline__ unsigned pack_bf16_split_l(float x, float y) {
    __nv_bfloat16 hx = __float2bfloat16(x), hy = __float2bfloat16(y);
    __nv_bfloat16 lx = __float2bfloat16(x - __bfloat162float(hx));
    __nv_bfloat16 ly = __float2bfloat16(y - __bfloat162float(hy));
    return (unsigned)__bfloat16_as_ushort(lx) | ((unsigned)__bfloat16_as_ushort(ly) << 16);
}

// ============================================================
// init: coalesced. 16 CTAs x 256 thr, 64 codes/CTA.
// exact ||e||^2 (sequential UNFUSED) + bf16 split + zero accums.
// ============================================================
__global__ __launch_bounds__(256) void vq_init(const float* __restrict__ emb) {
    __shared__ float es[64][65];
    int tid = threadIdx.x;
    int c0  = blockIdx.x * 64;
#pragma unroll
    for (int i = 0; i < 16; i++) {
        int idx = tid + i * 256;
        int r = idx >> 6, c = idx & 63;
        es[r][c] = emb[(c0 + r) * DIM + c];
    }
    if (blockIdx.x == 0) {
#pragma unroll
        for (int q = 0; q < 4; q++) g_counts[tid + q * 256] = 0.0f;
        if (tid == 0) { g_mse = 0.0; g_edist = 0.0; g_amb_cnt = 0; }
    }
    __syncthreads();
    if (tid < 64) {
        float s = 0.0f;
#pragma unroll
        for (int k = 0; k < DIM; k++) {
            float sq = __fmul_rn(es[tid][k], es[tid][k]);
            s = __fadd_rn(s, sq);
        }
        g_en[c0 + tid] = s;
    }
#pragma unroll
    for (int i = 0; i < 16; i++) {
        int idx = tid + i * 256;
        int r = idx >> 6, c = idx & 63;
        float v = es[r][c];
        __nv_bfloat16 h = __float2bfloat16(v);
        __nv_bfloat16 l = __float2bfloat16(v - __bfloat162float(h));
        g_esplit[(c0 + r) * 128 + c]      = h;
        g_esplit[(c0 + r) * 128 + 64 + c] = l;
    }
}

// ============================================================
// prep-lite: exact ||z||^2 per row (sequential UNFUSED) only.
// ============================================================
__global__ __launch_bounds__(256) void vq_prep(const float* __restrict__ z) {
    __shared__ float zs[64][65];
    int tid = threadIdx.x;
    int r0  = blockIdx.x * 64;
#pragma unroll
    for (int i = 0; i < 16; i++) {
        int idx = tid + i * 256;
        int r = idx >> 6, c = idx & 63;
        zs[r][c] = z[(r0 + r) * DIM + c];
    }
    __syncthreads();
    if (tid < 64) {
        float s = 0.0f;
#pragma unroll
        for (int k = 0; k < DIM; k++) {
            float sq = __fmul_rn(zs[tid][k], zs[tid][k]);
            s = __fadd_rn(s, sq);
        }
        g_zsq[r0 + tid] = s;
    }
}

// ============================================================
// codebook pairwise distances (e_loss) — unchanged, validated.
// ============================================================
__global__ __launch_bounds__(256) void vq_pairs(const float* __restrict__ emb) {
    __shared__ float ei[8][DIM];
    __shared__ float ej[128][LDE];
    __shared__ float eni_s[8];
    __shared__ float red[8];
    int tid = threadIdx.x;
    int i0  = blockIdx.x * 8;

    for (int v = tid; v < 8 * DIM; v += 256)
        ei[v >> 6][v & 63] = emb[i0 * DIM + v];
    if (tid < 8) eni_s[tid] = g_en[i0 + tid];

    float sum = 0.0f;
    for (int jc = 0; jc < NE; jc += 128) {
        __syncthreads();
#pragma unroll
        for (int t = 0; t < 8; t++) {
            int v  = tid + t * 256;
            int jl = v >> 4, c4 = (v & 15) << 2;
            float4 f = *reinterpret_cast<const float4*>(emb + (jc + jl) * DIM + c4);
            ej[jl][c4 + 0] = f.x; ej[jl][c4 + 1] = f.y;
            ej[jl][c4 + 2] = f.z; ej[jl][c4 + 3] = f.w;
        }
        __syncthreads();
        int il = tid >> 5, lane = tid & 31;
#pragma unroll
        for (int jj = 0; jj < 4; jj++) {
            int jl = lane + 32 * jj;
            float dot = 0.0f;
#pragma unroll 16
            for (int k = 0; k < DIM; k++)
                dot = fmaf(ei[il][k], ej[jl][k], dot);
            float d2 = eni_s[il] + g_en[jc + jl] - 2.0f * dot;
            sum += sqrtf(fmaxf(d2, 0.0f));
        }
    }
#pragma unroll
    for (int off = 16; off > 0; off >>= 1)
        sum += __shfl_down_sync(0xffffffffu, sum, off);
    if ((tid & 31) == 0) red[tid >> 5] = sum;
    __syncthreads();
    if (tid == 0) {
        float s = 0.0f;
#pragma unroll
        for (int w = 0; w < 8; w++) s += red[w];
        atomicAdd(&g_edist, (double)s);
    }
}

// ============================================================
// filter v3 (fused): split-bf16 MMA scoring + (min1,min2) +
// full emit for unambiguous rows.
// 256 thr = 8 warps, each warp 2 m-tiles (32 rows) -> 256 rows/CTA.
// Each B ldmatrix.x4 feeds 4 MMAs (smem wavefronts halved).
// K=192: ks 0-3 zh*eh, 4-7 zh*el, 8-11 zl*eh.
// ============================================================
__global__ __launch_bounds__(256, 2) void vq_filter(const float* __restrict__ z,
                                                    const float* __restrict__ emb,
                                                    float* __restrict__ out) {
    extern __shared__ __nv_bfloat16 sm[];
    __nv_bfloat16* As = sm;                           // [256][LDA]
    __nv_bfloat16* Bs = sm + MROWS * LDA;             // [128][LDA]
    float* en_s = (float*)(sm + (MROWS + 128) * LDA); // [128]
    int*   s_res = (int*)(en_s + 128);                // [256]
    float* red   = (float*)(s_res + MROWS);           // [8]

    const int tid = threadIdx.x, lane = tid & 31, w = tid >> 5;
    const int m0 = blockIdx.x * MROWS;

    // stage A: load z fp32 coalesced, split to bf16 (h|l) in place
    const float4* z4 = (const float4*)(z + (size_t)m0 * DIM);
#pragma unroll
    for (int i = 0; i < 16; i++) {
        int idx = tid + i * 256;
        int r = idx >> 4, q = idx & 15;
        float4 f = z4[r * 16 + q];
        uint2 hp, lp;
        hp.x = pack_bf16_split_h(f.x, f.y); hp.y = pack_bf16_split_h(f.z, f.w);
        lp.x = pack_bf16_split_l(f.x, f.y); lp.y = pack_bf16_split_l(f.z, f.w);
        *(uint2*)(As + r * LDA + q * 4)      = hp;
        *(uint2*)(As + r * LDA + 64 + q * 4) = lp;
    }
    __syncthreads();

    // A fragments: f 0-3 = zh k0..63, f 4-7 = zl ; 2 m-tiles per warp
    unsigned afr[8][2][4];
    unsigned abase = (unsigned)__cvta_generic_to_shared(As);
    {
        int acol8 = (lane >> 4) * 8;
#pragma unroll
        for (int f = 0; f < 8; f++) {
            int aoff = (f < 4) ? 16 * f : 64 + 16 * (f - 4);
#pragma unroll
            for (int m = 0; m < 2; m++) {
                int arow = w * 32 + m * 16 + (lane & 15);
                ldmx4(afr[f][m], abase + (unsigned)(arow * LDA + aoff + acol8) * 2u);
            }
        }
    }

    // min-tracking: slot = m*2+s -> row  w*32 + m*16 + (lane>>2) + 8*s
    float m1v[4], m2v[4]; int m1i[4];
#pragma unroll
    for (int s = 0; s < 4; s++) { m1v[s] = FLT_MAX; m2v[s] = FLT_MAX; m1i[s] = 0; }

    unsigned bbase = (unsigned)__cvta_generic_to_shared(Bs);
    const uint4* esp4 = (const uint4*)g_esplit;
    const int brow_in = ((lane >> 4) << 3) + (lane & 7);
    const int bcol8   = ((lane >> 3) & 1) * 8;
    const int ccol    = 2 * (lane & 3);

    for (int ch = 0; ch < 8; ch++) {
        const int cb = ch * 128;
        __syncthreads();                              // Bs free from previous chunk
#pragma unroll
        for (int i = 0; i < 8; i++) {
            int idx = tid + i * 256;
            int r = idx >> 4, q = idx & 15;
            *(uint4*)((char*)Bs + r * (LDA * 2) + q * 16) = esp4[(cb + r) * 16 + q];
        }
        if (tid < 128) en_s[tid] = g_en[cb + tid];
        __syncthreads();

#pragma unroll 1
        for (int ntp = 0; ntp < 8; ntp++) {           // 16 codes per iter
            float acc[2][2][4];
#pragma unroll
            for (int m = 0; m < 2; m++)
#pragma unroll
                for (int g = 0; g < 2; g++)
#pragma unroll
                    for (int q = 0; q < 4; q++) acc[m][g][q] = 0.0f;

            const int brow = ntp * 16 + brow_in;
#pragma unroll
            for (int ks = 0; ks < 12; ks++) {
                int f    = (ks < 8) ? (ks & 3) : (4 + (ks & 3));
                int boff = (ks < 4) ? 16 * ks : (ks < 8) ? 64 + 16 * (ks - 4) : 16 * (ks - 8);
                unsigned bf[4];
                ldmx4(bf, bbase + (unsigned)(brow * LDA + boff + bcol8) * 2u);
                mma16816(acc[0][0], afr[f][0], bf);
                mma16816(acc[0][1], afr[f][0], bf + 2);
                mma16816(acc[1][0], afr[f][1], bf);
                mma16816(acc[1][1], afr[f][1], bf + 2);
            }
            // epilogue: per slot codes ascend: g00, g00+1, g10, g10+1
            int l0 = ntp * 16 + ccol;
            float en00 = en_s[l0],     en01 = en_s[l0 + 1];
            float en10 = en_s[l0 + 8], en11 = en_s[l0 + 9];
            int g00 = cb + l0, g10 = g00 + 8;
#pragma unroll
            for (int m = 0; m < 2; m++)
#pragma unroll
            for (int s = 0; s < 2; s++) {
                int sl = m * 2 + s;
                float u0 = fmaf(-2.0f, acc[m][0][2 * s],     en00);
                float u1 = fmaf(-2.0f, acc[m][0][2 * s + 1], en01);
                float u2 = fmaf(-2.0f, acc[m][1][2 * s],     en10);
                float u3 = fmaf(-2.0f, acc[m][1][2 * s + 1], en11);
                if (u0 < m1v[sl]) { m2v[sl] = m1v[sl]; m1v[sl] = u0; m1i[sl] = g00; }
                else if (u0 < m2v[sl]) m2v[sl] = u0;
                if (u1 < m1v[sl]) { m2v[sl] = m1v[sl]; m1v[sl] = u1; m1i[sl] = g00 + 1; }
                else if (u1 < m2v[sl]) m2v[sl] = u1;
                if (u2 < m1v[sl]) { m2v[sl] = m1v[sl]; m1v[sl] = u2; m1i[sl] = g10; }
                else if (u2 < m2v[sl]) m2v[sl] = u2;
                if (u3 < m1v[sl]) { m2v[sl] = m1v[sl]; m1v[sl] = u3; m1i[sl] = g10 + 1; }
                else if (u3 < m2v[sl]) m2v[sl] = u3;
            }
        }
    }

    // quad reduce (cols live in lanes xor 1,2); lexicographic (val, idx)
#pragma unroll
    for (int off = 1; off <= 2; off <<= 1) {
#pragma unroll
        for (int s = 0; s < 4; s++) {
            float ov = __shfl_xor_sync(0xffffffffu, m1v[s], off);
            int   oi = __shfl_xor_sync(0xffffffffu, m1i[s], off);
            float o2 = __shfl_xor_sync(0xffffffffu, m2v[s], off);
            float nm2 = fminf(fmaxf(m1v[s], ov), fminf(m2v[s], o2));
            if (ov < m1v[s] || (ov == m1v[s] && oi < m1i[s])) { m1v[s] = ov; m1i[s] = oi; }
            m2v[s] = nm2;
        }
    }
    if ((lane & 3) == 0) {
#pragma unroll
        for (int m = 0; m < 2; m++)
#pragma unroll
        for (int s = 0; s < 2; s++) {
            int sl = m * 2 + s;
            int rl = w * 32 + m * 16 + (lane >> 2) + 8 * s;
            bool amb = (m2v[sl] - m1v[sl] < DELTA);
            s_res[rl] = m1i[sl] | (amb ? 0x80000000 : 0);
            if (amb) {
                int p = atomicAdd(&g_amb_cnt, 1);
                g_amb_rows[p] = m0 + rl;
            }
        }
    }
    __syncthreads();

    // fused emit: unambiguous rows only (rescan owns flagged rows)
    float* zq   = out + ZQ_OFF;
    float* oidx = out + IDX_OFF;
    int col = tid & 63, r0 = tid >> 6;
    float lsum = 0.0f;
#pragma unroll 4
    for (int it = 0; it < 64; ++it) {
        int rl = r0 + 4 * it;
        int res = s_res[rl];
        if (res >= 0) {
            float q  = emb[res * DIM + col];
            float zh = __bfloat162float(As[rl * LDA + col]);
            float zl = __bfloat162float(As[rl * LDA + 64 + col]);
            float zv = __fadd_rn(zh, zl);           // z to within 4e-6 rel (mse-only)
            zq[(m0 + rl) * DIM + col] = q;
            float d = q - zv;
            lsum = fmaf(d, d, lsum);
            if (col == 0) {
                oidx[m0 + rl] = (float)res;
                atomicAdd(&g_counts[res], 1.0f);
            }
        }
    }
#pragma unroll
    for (int off = 16; off > 0; off >>= 1)
        lsum += __shfl_down_sync(0xffffffffu, lsum, off);
    if (lane == 0) red[w] = lsum;
    __syncthreads();
    if (tid == 0) {
        float s = 0.0f;
#pragma unroll
        for (int q = 0; q < 8; q++) s += red[q];
        atomicAdd(&g_mse, (double)s);
    }
}

// ============================================================
// rescan v3: EXACT reference arithmetic, one warp per flagged
// row; owns ALL outputs for its rows (zq, idx, count, mse).
// ============================================================
__global__ __launch_bounds__(256) void vq_rescan(const float* __restrict__ z,
                                                 const float* __restrict__ emb,
                                                 float* __restrict__ out) {
    __shared__ float zr[8][64];
    int tid = threadIdx.x, lane = tid & 31, w = tid >> 5;
    int wg = blockIdx.x * 8 + w;
    int nW = gridDim.x * 8;
    int cnt = g_amb_cnt;
    float* zq   = out + ZQ_OFF;
    float* oidx = out + IDX_OFF;

    for (int a = wg; a < cnt; a += nW) {
        int row = g_amb_rows[a];
        float2 zv = *(const float2*)(z + row * DIM + 2 * lane);
        zr[w][2 * lane] = zv.x; zr[w][2 * lane + 1] = zv.y;
        __syncwarp();
        float zsq = g_zsq[row];

        float bv = FLT_MAX; int bi = 0;
        for (int c = lane; c < NE; c += 32) {       // per-lane codes ascend
            const float4* e4 = (const float4*)(emb + c * DIM);
            float dot = 0.0f;
#pragma unroll
            for (int k4 = 0; k4 < 16; k4++) {
                float4 ev = __ldg(&e4[k4]);
                dot = fmaf(zr[w][4 * k4 + 0], ev.x, dot);
                dot = fmaf(zr[w][4 * k4 + 1], ev.y, dot);
                dot = fmaf(zr[w][4 * k4 + 2], ev.z, dot);
                dot = fmaf(zr[w][4 * k4 + 3], ev.w, dot);
            }
            float t = __fadd_rn(zsq, g_en[c]);
            float s = __fadd_rn(t, -2.0f * dot);
            if (s < bv) { bv = s; bi = c; }
        }
#pragma unroll
        for (int off = 16; off > 0; off >>= 1) {
            float ov = __shfl_down_sync(0xffffffffu, bv, off);
            int   oi = __shfl_down_sync(0xffffffffu, bi, off);
            if (ov < bv || (ov == bv && oi < bi)) { bv = ov; bi = oi; }
        }
        bi = __shfl_sync(0xffffffffu, bi, 0);

        // outputs for this row
        float q0 = emb[bi * DIM + 2 * lane], q1 = emb[bi * DIM + 2 * lane + 1];
        float z0 = zr[w][2 * lane],          z1 = zr[w][2 * lane + 1];
        zq[row * DIM + 2 * lane]     = q0;
        zq[row * DIM + 2 * lane + 1] = q1;
        float d0 = q0 - z0, d1 = q1 - z1;
        float ls = fmaf(d0, d0, d1 * d1);
#pragma unroll
        for (int off = 16; off > 0; off >>= 1)
            ls += __shfl_down_sync(0xffffffffu, ls, off);
        if (lane == 0) {
            oidx[row] = (float)bi;
            atomicAdd(&g_counts[bi], 1.0f);
            atomicAdd(&g_mse, (double)ls);
        }
        __syncwarp();
    }
}

// ============================================================
// finalize: perplexity + loss scalars (validated).
// ============================================================
__global__ void vq_finalize(float* __restrict__ out) {
    __shared__ float red[32];
    int tid = threadIdx.x;   // 1024 threads
    float p = g_counts[tid] * (1.0f / (float)NROWS);
    float h = -p * logf(p + 1e-10f);
#pragma unroll
    for (int off = 16; off > 0; off >>= 1)
        h += __shfl_down_sync(0xffffffffu, h, off);
    if ((tid & 31) == 0) red[tid >> 5] = h;
    __syncthreads();
    if (tid == 0) {
        float H = 0.0f;
#pragma unroll
        for (int w = 0; w < 32; w++) H += red[w];
        float perp = expf(H);
        double mse = g_mse / (double)(NROWS * DIM);
        double mean_tril = (g_edist * 0.5) / ((double)NE * (double)NE);
        double e_loss = exp(-mean_tril / 0.1);
        out[0]        = (float)(1.25 * mse + e_loss);
        out[PERP_OFF] = perp;
    }
}

// ============================================================
extern "C" void kernel_launch(void* const* d_in, const int* in_sizes, int n_in,
                              void* d_out, int out_size) {
    const float* z   = (const float*)d_in[0];
    const float* emb = (const float*)d_in[1];
    float* out = (float*)d_out;

    const int fsmem = (MROWS + 128) * LDA * 2 + 128 * 4 + MROWS * 4 + 8 * 4; // 106,016 B
    cudaFuncSetAttribute(vq_filter, cudaFuncAttributeMaxDynamicSharedMemorySize, fsmem);

    vq_init<<<NE / 64, 256>>>(emb);
    vq_prep<<<NROWS / 64, 256>>>(z);
    vq_pairs<<<NE / 8, 256>>>(emb);
    vq_filter<<<NROWS / MROWS, 256, fsmem>>>(z, emb, out);
    vq_rescan<<<128, 256>>>(z, emb, out);
    vq_finalize<<<1, 1024>>>(out);
}

// round 10
// speedup vs baseline: 1.3999x; 1.3999x over previous
#include <cuda_runtime.h>
#include <cuda_bf16.h>
#include <math.h>
#include <float.h>

#define NROWS 65536      // 32*32*64
#define DIM   64
#define NE    1024
#define LDE   65         // vq_pairs tile ld

// Output layout (float32, return-order flatten)
#define ZQ_OFF   1
#define PERP_OFF (1 + NROWS*DIM)
#define IDX_OFF  (2 + NROWS*DIM)

#define DELTA 4e-5f      // ambiguity margin (> 2*approx_err + 2*ulp(64) window)
#define LDA   136        // padded split-row ld in bf16 (272B = 17*16B)

// ---- scratch (no allocations allowed) ----
__device__ float  g_counts[NE];
__device__ float  g_en[NE];
__device__ float  g_zsq[NROWS];
__device__ int    g_idx[NROWS];
__device__ int    g_amb_rows[NROWS];
__device__ int    g_amb_cnt;
__device__ double g_mse;
__device__ double g_edist;
__device__ __nv_bfloat16 g_esplit[NE * 128];       // [code][ eh(64) | el(64) ]
__device__ __nv_bfloat16 g_zsplit[NROWS * 128];    // [row ][ zh(64) | zl(64) ]

// ============================================================
// PTX helpers (fragment layouts validated bitwise in R5/R6)
// ============================================================
__device__ __forceinline__ void ldmx4(unsigned* r, unsigned addr) {
    asm volatile("ldmatrix.sync.aligned.m8n8.x4.shared.b16 {%0,%1,%2,%3}, [%4];"
                 : "=r"(r[0]), "=r"(r[1]), "=r"(r[2]), "=r"(r[3]) : "r"(addr));
}
__device__ __forceinline__ void mma16816(float* c, const unsigned* a, const unsigned* b) {
    asm volatile("mma.sync.aligned.m16n8k16.row.col.f32.bf16.bf16.f32 "
                 "{%0,%1,%2,%3}, {%4,%5,%6,%7}, {%8,%9}, {%0,%1,%2,%3};"
                 : "+f"(c[0]), "+f"(c[1]), "+f"(c[2]), "+f"(c[3])
                 : "r"(a[0]), "r"(a[1]), "r"(a[2]), "r"(a[3]), "r"(b[0]), "r"(b[1]));
}

// ============================================================
// init: coalesced. 16 CTAs x 256 thr, 64 codes/CTA.
// exact ||e||^2 (sequential UNFUSED) + bf16 split + zero accums.
// ============================================================
__global__ __launch_bounds__(256) void vq_init(const float* __restrict__ emb) {
    __shared__ float es[64][65];
    int tid = threadIdx.x;
    int c0  = blockIdx.x * 64;
#pragma unroll
    for (int i = 0; i < 16; i++) {
        int idx = tid + i * 256;
        int r = idx >> 6, c = idx & 63;
        es[r][c] = emb[(c0 + r) * DIM + c];
    }
    if (blockIdx.x == 0) {
#pragma unroll
        for (int q = 0; q < 4; q++) g_counts[tid + q * 256] = 0.0f;
        if (tid == 0) { g_mse = 0.0; g_edist = 0.0; g_amb_cnt = 0; }
    }
    __syncthreads();
    if (tid < 64) {
        float s = 0.0f;
#pragma unroll
        for (int k = 0; k < DIM; k++) {
            float sq = __fmul_rn(es[tid][k], es[tid][k]);
            s = __fadd_rn(s, sq);
        }
        g_en[c0 + tid] = s;
    }
#pragma unroll
    for (int i = 0; i < 16; i++) {
        int idx = tid + i * 256;
        int r = idx >> 6, c = idx & 63;
        float v = es[r][c];
        __nv_bfloat16 h = __float2bfloat16(v);
        __nv_bfloat16 l = __float2bfloat16(v - __bfloat162float(h));
        g_esplit[(c0 + r) * 128 + c]      = h;
        g_esplit[(c0 + r) * 128 + 64 + c] = l;
    }
}

// ============================================================
// prep: exact ||z||^2 per row (sequential UNFUSED) + bf16 split.
// ============================================================
__global__ __launch_bounds__(256) void vq_prep(const float* __restrict__ z) {
    __shared__ float zs[64][65];
    int tid = threadIdx.x;
    int r0  = blockIdx.x * 64;
#pragma unroll
    for (int i = 0; i < 16; i++) {
        int idx = tid + i * 256;
        int r = idx >> 6, c = idx & 63;
        zs[r][c] = z[(r0 + r) * DIM + c];
    }
    __syncthreads();
    if (tid < 64) {
        float s = 0.0f;
#pragma unroll
        for (int k = 0; k < DIM; k++) {
            float sq = __fmul_rn(zs[tid][k], zs[tid][k]);
            s = __fadd_rn(s, sq);
        }
        g_zsq[r0 + tid] = s;
    }
#pragma unroll
    for (int i = 0; i < 16; i++) {
        int idx = tid + i * 256;
        int r = idx >> 6, c = idx & 63;
        float v = zs[r][c];
        __nv_bfloat16 h = __float2bfloat16(v);
        __nv_bfloat16 l = __float2bfloat16(v - __bfloat162float(h));
        g_zsplit[(r0 + r) * 128 + c]      = h;
        g_zsplit[(r0 + r) * 128 + 64 + c] = l;
    }
}

// ============================================================
// codebook pairwise distances (e_loss) — unchanged, validated.
// ============================================================
__global__ __launch_bounds__(256) void vq_pairs(const float* __restrict__ emb) {
    __shared__ float ei[8][DIM];
    __shared__ float ej[128][LDE];
    __shared__ float eni_s[8];
    __shared__ float red[8];
    int tid = threadIdx.x;
    int i0  = blockIdx.x * 8;

    for (int v = tid; v < 8 * DIM; v += 256)
        ei[v >> 6][v & 63] = emb[i0 * DIM + v];
    if (tid < 8) eni_s[tid] = g_en[i0 + tid];

    float sum = 0.0f;
    for (int jc = 0; jc < NE; jc += 128) {
        __syncthreads();
#pragma unroll
        for (int t = 0; t < 8; t++) {
            int v  = tid + t * 256;
            int jl = v >> 4, c4 = (v & 15) << 2;
            float4 f = *reinterpret_cast<const float4*>(emb + (jc + jl) * DIM + c4);
            ej[jl][c4 + 0] = f.x; ej[jl][c4 + 1] = f.y;
            ej[jl][c4 + 2] = f.z; ej[jl][c4 + 3] = f.w;
        }
        __syncthreads();
        int il = tid >> 5, lane = tid & 31;
#pragma unroll
        for (int jj = 0; jj < 4; jj++) {
            int jl = lane + 32 * jj;
            float dot = 0.0f;
#pragma unroll 16
            for (int k = 0; k < DIM; k++)
                dot = fmaf(ei[il][k], ej[jl][k], dot);
            float d2 = eni_s[il] + g_en[jc + jl] - 2.0f * dot;
            sum += sqrtf(fmaxf(d2, 0.0f));
        }
    }
#pragma unroll
    for (int off = 16; off > 0; off >>= 1)
        sum += __shfl_down_sync(0xffffffffu, sum, off);
    if ((tid & 31) == 0) red[tid >> 5] = sum;
    __syncthreads();
    if (tid == 0) {
        float s = 0.0f;
#pragma unroll
        for (int w = 0; w < 8; w++) s += red[w];
        atomicAdd(&g_edist, (double)s);
    }
}

// ============================================================
// filter (R6, measured 107us): split-bf16 MMA + per-row (min1,min2).
// 256 thr (8 warps x 16-row mtile) = 128 rows/CTA.
// Codes in 8 chunks of 128; B frags via ldmatrix.x4 (2 ntiles).
// K=192: ks 0-3 zh*eh, 4-7 zh*el, 8-11 zl*eh.
// ============================================================
__global__ __launch_bounds__(256, 2) void vq_filter(void) {
    extern __shared__ __nv_bfloat16 sm[];
    __nv_bfloat16* As = sm;                         // [128][LDA]
    __nv_bfloat16* Bs = sm + 128 * LDA;             // [128][LDA]
    float* en_s = (float*)(sm + 2 * 128 * LDA);     // [128]

    const int tid = threadIdx.x, lane = tid & 31, w = tid >> 5;
    const int m0 = blockIdx.x * 128;

    // stage A (zsplit rows) via uint4: 2048 / 256 thr = 8 each
    const uint4* zsp4 = (const uint4*)g_zsplit;     // 16 uint4 per row
#pragma unroll
    for (int i = 0; i < 8; i++) {
        int idx = tid + i * 256;
        int r = idx >> 4, q = idx & 15;
        *(uint4*)((char*)As + r * (LDA * 2) + q * 16) = zsp4[(m0 + r) * 16 + q];
    }
    __syncthreads();

    // A fragments: f 0-3 = zh k0..63, f 4-7 = zl
    unsigned afr[8][4];
    unsigned abase = (unsigned)__cvta_generic_to_shared(As);
    {
        int arow = w * 16 + (lane & 15);
        int acol8 = (lane >> 4) * 8;
#pragma unroll
        for (int f = 0; f < 8; f++) {
            int aoff = (f < 4) ? 16 * f : 64 + 16 * (f - 4);
            ldmx4(afr[f], abase + (unsigned)(arow * LDA + aoff + acol8) * 2u);
        }
    }

    float m1v[2], m2v[2]; int m1i[2];
#pragma unroll
    for (int s = 0; s < 2; s++) { m1v[s] = FLT_MAX; m2v[s] = FLT_MAX; m1i[s] = 0; }

    unsigned bbase = (unsigned)__cvta_generic_to_shared(Bs);
    const uint4* esp4 = (const uint4*)g_esplit;
    const int brow_in = ((lane >> 4) << 3) + (lane & 7);   // 0..15 pattern
    const int bcol8   = ((lane >> 3) & 1) * 8;
    const int ccol    = 2 * (lane & 3);

    for (int ch = 0; ch < 8; ch++) {
        const int cb = ch * 128;
        __syncthreads();                            // Bs free from previous chunk
#pragma unroll
        for (int i = 0; i < 8; i++) {
            int idx = tid + i * 256;
            int r = idx >> 4, q = idx & 15;
            *(uint4*)((char*)Bs + r * (LDA * 2) + q * 16) = esp4[(cb + r) * 16 + q];
        }
        if (tid < 128) en_s[tid] = g_en[cb + tid];
        __syncthreads();

#pragma unroll 1
        for (int ntp = 0; ntp < 8; ntp++) {         // 16 codes per iter
            float acc0[4] = {0,0,0,0}, acc1[4] = {0,0,0,0};
            const int brow = ntp * 16 + brow_in;
#pragma unroll
            for (int ks = 0; ks < 12; ks++) {
                int f    = (ks < 8) ? (ks & 3) : (4 + (ks & 3));
                int boff = (ks < 4) ? 16 * ks : (ks < 8) ? 64 + 16 * (ks - 4) : 16 * (ks - 8);
                unsigned bf[4];
                ldmx4(bf, bbase + (unsigned)(brow * LDA + boff + bcol8) * 2u);
                mma16816(acc0, afr[f], bf);         // codes ntp*16 + 0..7
                mma16816(acc1, afr[f], bf + 2);     // codes ntp*16 + 8..15
            }
            // epilogue: codes ascend per thread: grp 0 (cols+0..7) then grp 1 (+8..15)
            int l0 = ntp * 16 + ccol;
            float en00 = en_s[l0],     en01 = en_s[l0 + 1];
            float en10 = en_s[l0 + 8], en11 = en_s[l0 + 9];
            int g00 = cb + l0, g10 = cb + l0 + 8;
#pragma unroll
            for (int s = 0; s < 2; s++) {           // s=0: row lane>>2 ; s=1: +8
                float u0 = fmaf(-2.0f, acc0[2 * s],     en00);
                float u1 = fmaf(-2.0f, acc0[2 * s + 1], en01);
                float u2 = fmaf(-2.0f, acc1[2 * s],     en10);
                float u3 = fmaf(-2.0f, acc1[2 * s + 1], en11);
                if (u0 < m1v[s]) { m2v[s] = m1v[s]; m1v[s] = u0; m1i[s] = g00; }
                else if (u0 < m2v[s]) m2v[s] = u0;
                if (u1 < m1v[s]) { m2v[s] = m1v[s]; m1v[s] = u1; m1i[s] = g00 + 1; }
                else if (u1 < m2v[s]) m2v[s] = u1;
                if (u2 < m1v[s]) { m2v[s] = m1v[s]; m1v[s] = u2; m1i[s] = g10; }
                else if (u2 < m2v[s]) m2v[s] = u2;
                if (u3 < m1v[s]) { m2v[s] = m1v[s]; m1v[s] = u3; m1i[s] = g10 + 1; }
                else if (u3 < m2v[s]) m2v[s] = u3;
            }
        }
    }

    // quad reduce (cols live in lanes xor 1,2); lexicographic (val, idx)
#pragma unroll
    for (int off = 1; off <= 2; off <<= 1) {
#pragma unroll
        for (int s = 0; s < 2; s++) {
            float ov = __shfl_xor_sync(0xffffffffu, m1v[s], off);
            int   oi = __shfl_xor_sync(0xffffffffu, m1i[s], off);
            float o2 = __shfl_xor_sync(0xffffffffu, m2v[s], off);
            float nm2 = fminf(fmaxf(m1v[s], ov), fminf(m2v[s], o2));
            if (ov < m1v[s] || (ov == m1v[s] && oi < m1i[s])) { m1v[s] = ov; m1i[s] = oi; }
            m2v[s] = nm2;
        }
    }
    if ((lane & 3) == 0) {
#pragma unroll
        for (int s = 0; s < 2; s++) {
            int grow = m0 + w * 16 + (lane >> 2) + 8 * s;
            g_idx[grow] = m1i[s];
            if (m2v[s] - m1v[s] < DELTA) {
                int p = atomicAdd(&g_amb_cnt, 1);
                g_amb_rows[p] = grow;
            }
        }
    }
}

// ============================================================
// rescan (tiled): EXACT reference arithmetic over the compacted
// ambiguous-row list. 128-row tiles, fully coalesced, bounded.
//   d = fl( fl(zsq + en) - 2*dot ),  dot = seq ascending-k fmaf.
// ============================================================
#define MT  128
#define LDZ 65
__global__ __launch_bounds__(256) void vq_rescan(const float* __restrict__ z,
                                                 const float* __restrict__ emb) {
    extern __shared__ float smf[];
    float (*zs)[LDZ] = (float(*)[LDZ])smf;
    float (*es)[LDZ] = (float(*)[LDZ])(smf + MT * LDZ);
    float* szs = smf + 2 * MT * LDZ;               // [MT]
    int*   rows = (int*)(szs + MT);                // [MT]

    const int tid = threadIdx.x;
    const int tx  = tid & 15, ty = tid >> 4;
    const int cnt = g_amb_cnt;
    const int ntiles = (cnt + MT - 1) >> 7;

    for (int tile = blockIdx.x; tile < ntiles; tile += gridDim.x) {
        if (tid < MT) {
            int a = tile * MT + tid;
            rows[tid] = g_amb_rows[a < cnt ? a : cnt - 1];
        }
        __syncthreads();
        // gather z rows (coalesced within row)
#pragma unroll
        for (int t = 0; t < 8; t++) {
            int v = tid + t * 256;
            int r = v >> 4, c4 = (v & 15) << 2;
            float4 f = *reinterpret_cast<const float4*>(z + (size_t)rows[r] * DIM + c4);
            zs[r][c4 + 0] = f.x; zs[r][c4 + 1] = f.y;
            zs[r][c4 + 2] = f.z; zs[r][c4 + 3] = f.w;
        }
        __syncthreads();
        if (tid < MT) {
            float s = 0.0f;
#pragma unroll
            for (int k = 0; k < DIM; k++) {
                float sq = __fmul_rn(zs[tid][k], zs[tid][k]);
                s = __fadd_rn(s, sq);
            }
            szs[tid] = s;
        }
        __syncthreads();

        float Srow[8];
#pragma unroll
        for (int i = 0; i < 8; i++) Srow[i] = szs[ty + 16 * i];

        float minv[8]; int mini[8];
#pragma unroll
        for (int i = 0; i < 8; i++) { minv[i] = 3.4e38f; mini[i] = 0; }

        for (int n0 = 0; n0 < NE; n0 += 128) {
            __syncthreads();
#pragma unroll
            for (int t = 0; t < 8; t++) {
                int v = tid + t * 256;
                int cl = v >> 4, c4 = (v & 15) << 2;
                float4 f = *reinterpret_cast<const float4*>(emb + (n0 + cl) * DIM + c4);
                es[cl][c4 + 0] = f.x; es[cl][c4 + 1] = f.y;
                es[cl][c4 + 2] = f.z; es[cl][c4 + 3] = f.w;
            }
            __syncthreads();

            float dot[8][8];
#pragma unroll
            for (int i = 0; i < 8; i++)
#pragma unroll
                for (int j = 0; j < 8; j++) dot[i][j] = 0.0f;
#pragma unroll 8
            for (int k = 0; k < DIM; k++) {
                float a[8], b[8];
#pragma unroll
                for (int i = 0; i < 8; i++) a[i] = zs[ty + 16 * i][k];
#pragma unroll
                for (int j = 0; j < 8; j++) b[j] = es[tx + 16 * j][k];
#pragma unroll
                for (int i = 0; i < 8; i++)
#pragma unroll
                    for (int j = 0; j < 8; j++)
                        dot[i][j] = fmaf(a[i], b[j], dot[i][j]);
            }
#pragma unroll
            for (int j = 0; j < 8; j++) {
                int code = n0 + tx + 16 * j;
                float en = __ldg(&g_en[code]);
#pragma unroll
                for (int i = 0; i < 8; i++) {
                    float t = __fadd_rn(Srow[i], en);
                    float s = __fadd_rn(t, -2.0f * dot[i][j]);
                    if (s < minv[i]) { minv[i] = s; mini[i] = code; }
                }
            }
        }
#pragma unroll
        for (int off = 8; off > 0; off >>= 1) {
#pragma unroll
            for (int i = 0; i < 8; i++) {
                float ov = __shfl_down_sync(0xffffffffu, minv[i], off, 16);
                int   oi = __shfl_down_sync(0xffffffffu, mini[i], off, 16);
                if (ov < minv[i] || (ov == minv[i] && oi < mini[i])) {
                    minv[i] = ov; mini[i] = oi;
                }
            }
        }
        if (tx == 0) {
#pragma unroll
            for (int i = 0; i < 8; i++) {
                int sl = ty + 16 * i;
                if (tile * MT + sl < cnt) g_idx[rows[sl]] = mini[i];
            }
        }
        __syncthreads();
    }
}

// ============================================================
// emit: gather z_q, indices, histogram, mse (coalesced).
// ============================================================
__global__ __launch_bounds__(256) void vq_emit(const float* __restrict__ z,
                                               const float* __restrict__ emb,
                                               float* __restrict__ out) {
    __shared__ float red[8];
    int tid = threadIdx.x;
    int m0  = blockIdx.x * 128;
    float* zq   = out + ZQ_OFF;
    float* oidx = out + IDX_OFF;
    int col = tid & 63, r0 = tid >> 6;

    float lsum = 0.0f;
#pragma unroll 4
    for (int it = 0; it < 32; ++it) {
        int r   = m0 + r0 + 4 * it;
        int gi  = r * DIM + col;
        int idx = g_idx[r];
        float q  = emb[idx * DIM + col];
        float zv = z[gi];
        zq[gi] = q;
        float d = q - zv;
        lsum = fmaf(d, d, lsum);
        if (col == 0) {
            oidx[r] = (float)idx;
            atomicAdd(&g_counts[idx], 1.0f);
        }
    }
#pragma unroll
    for (int off = 16; off > 0; off >>= 1)
        lsum += __shfl_down_sync(0xffffffffu, lsum, off);
    if ((tid & 31) == 0) red[tid >> 5] = lsum;
    __syncthreads();
    if (tid == 0) {
        float s = 0.0f;
#pragma unroll
        for (int w = 0; w < 8; w++) s += red[w];
        atomicAdd(&g_mse, (double)s);
    }
}

// ============================================================
// finalize: perplexity + loss scalars (validated).
// ============================================================
__global__ void vq_finalize(float* __restrict__ out) {
    __shared__ float red[32];
    int tid = threadIdx.x;   // 1024 threads
    float p = g_counts[tid] * (1.0f / (float)NROWS);
    float h = -p * logf(p + 1e-10f);
#pragma unroll
    for (int off = 16; off > 0; off >>= 1)
        h += __shfl_down_sync(0xffffffffu, h, off);
    if ((tid & 31) == 0) red[tid >> 5] = h;
    __syncthreads();
    if (tid == 0) {
        float H = 0.0f;
#pragma unroll
        for (int w = 0; w < 32; w++) H += red[w];
        float perp = expf(H);
        double mse = g_mse / (double)(NROWS * DIM);
        double mean_tril = (g_edist * 0.5) / ((double)NE * (double)NE);
        double e_loss = exp(-mean_tril / 0.1);
        out[0]        = (float)(1.25 * mse + e_loss);
        out[PERP_OFF] = perp;
    }
}

// ============================================================
extern "C" void kernel_launch(void* const* d_in, const int* in_sizes, int n_in,
                              void* d_out, int out_size) {
    const float* z   = (const float*)d_in[0];
    const float* emb = (const float*)d_in[1];
    float* out = (float*)d_out;

    const int fsmem = 2 * 128 * LDA * 2 + 128 * 4;   // 70,144 B
    cudaFuncSetAttribute(vq_filter, cudaFuncAttributeMaxDynamicSharedMemorySize, fsmem);
    const int rsmem = (2 * MT * LDZ + MT) * (int)sizeof(float) + MT * (int)sizeof(int);
    cudaFuncSetAttribute(vq_rescan, cudaFuncAttributeMaxDynamicSharedMemorySize, rsmem);

    vq_init<<<NE / 64, 256>>>(emb);
    vq_prep<<<NROWS / 64, 256>>>(z);
    vq_pairs<<<NE / 8, 256>>>(emb);
    vq_filter<<<NROWS / 128, 256, fsmem>>>();
    vq_rescan<<<64, 256, rsmem>>>(z, emb);
    vq_emit<<<NROWS / 128, 256>>>(z, emb, out);
    vq_finalize<<<1, 1024>>>(out);
}

// round 11
// speedup vs baseline: 1.4957x; 1.0684x over previous
#include <cuda_runtime.h>
#include <cuda_bf16.h>
#include <math.h>
#include <float.h>

#define NROWS 65536      // 32*32*64
#define DIM   64
#define NE    1024
#define LDE   65         // vq_pairs tile ld

// Output layout (float32, return-order flatten)
#define ZQ_OFF   1
#define PERP_OFF (1 + NROWS*DIM)
#define IDX_OFF  (2 + NROWS*DIM)

#define DELTA 4e-5f      // ambiguity margin (validated R5-R10)
#define LDA   136        // padded split-row ld in bf16 (272B = 17*16B)
#define MROWS 256        // rows per filter CTA (2 m-tiles per warp)

// ---- scratch (no allocations allowed) ----
__device__ float  g_counts[NE];
__device__ float  g_en[NE];
__device__ int    g_idx[NROWS];
__device__ int    g_amb_rows[NROWS];
__device__ int    g_amb_cnt;
__device__ double g_mse;
__device__ double g_edist;
__device__ __nv_bfloat16 g_esplit[NE * 128];       // [code][ eh(64) | el(64) ]

// ============================================================
// PTX helpers (fragment layouts validated bitwise R5/R6/R7)
// ============================================================
__device__ __forceinline__ void ldmx4(unsigned* r, unsigned addr) {
    asm volatile("ldmatrix.sync.aligned.m8n8.x4.shared.b16 {%0,%1,%2,%3}, [%4];"
                 : "=r"(r[0]), "=r"(r[1]), "=r"(r[2]), "=r"(r[3]) : "r"(addr));
}
__device__ __forceinline__ void mma16816(float* c, const unsigned* a, const unsigned* b) {
    asm volatile("mma.sync.aligned.m16n8k16.row.col.f32.bf16.bf16.f32 "
                 "{%0,%1,%2,%3}, {%4,%5,%6,%7}, {%8,%9}, {%0,%1,%2,%3};"
                 : "+f"(c[0]), "+f"(c[1]), "+f"(c[2]), "+f"(c[3])
                 : "r"(a[0]), "r"(a[1]), "r"(a[2]), "r"(a[3]), "r"(b[0]), "r"(b[1]));
}
__device__ __forceinline__ unsigned pack_bf16_h(float x, float y) {
    __nv_bfloat16 hx = __float2bfloat16(x), hy = __float2bfloat16(y);
    return (unsigned)__bfloat16_as_ushort(hx) | ((unsigned)__bfloat16_as_ushort(hy) << 16);
}
__device__ __forceinline__ unsigned pack_bf16_l(float x, float y) {
    __nv_bfloat16 hx = __float2bfloat16(x), hy = __float2bfloat16(y);
    __nv_bfloat16 lx = __float2bfloat16(x - __bfloat162float(hx));
    __nv_bfloat16 ly = __float2bfloat16(y - __bfloat162float(hy));
    return (unsigned)__bfloat16_as_ushort(lx) | ((unsigned)__bfloat16_as_ushort(ly) << 16);
}

// ============================================================
// init: coalesced. exact ||e||^2 (sequential UNFUSED) + bf16
// split of the codebook + zero accumulators.
// ============================================================
__global__ __launch_bounds__(256) void vq_init(const float* __restrict__ emb) {
    __shared__ float es[64][65];
    int tid = threadIdx.x;
    int c0  = blockIdx.x * 64;
#pragma unroll
    for (int i = 0; i < 16; i++) {
        int idx = tid + i * 256;
        int r = idx >> 6, c = idx & 63;
        es[r][c] = emb[(c0 + r) * DIM + c];
    }
    if (blockIdx.x == 0) {
#pragma unroll
        for (int q = 0; q < 4; q++) g_counts[tid + q * 256] = 0.0f;
        if (tid == 0) { g_mse = 0.0; g_edist = 0.0; g_amb_cnt = 0; }
    }
    __syncthreads();
    if (tid < 64) {
        float s = 0.0f;
#pragma unroll
        for (int k = 0; k < DIM; k++) {
            float sq = __fmul_rn(es[tid][k], es[tid][k]);
            s = __fadd_rn(s, sq);
        }
        g_en[c0 + tid] = s;
    }
#pragma unroll
    for (int i = 0; i < 16; i++) {
        int idx = tid + i * 256;
        int r = idx >> 6, c = idx & 63;
        float v = es[r][c];
        __nv_bfloat16 h = __float2bfloat16(v);
        __nv_bfloat16 l = __float2bfloat16(v - __bfloat162float(h));
        g_esplit[(c0 + r) * 128 + c]      = h;
        g_esplit[(c0 + r) * 128 + 64 + c] = l;
    }
}

// ============================================================
// codebook pairwise distances (e_loss) — unchanged, validated.
// Runs on a forked stream, overlapped with vq_filter.
// ============================================================
__global__ __launch_bounds__(256) void vq_pairs(const float* __restrict__ emb) {
    __shared__ float ei[8][DIM];
    __shared__ float ej[128][LDE];
    __shared__ float eni_s[8];
    __shared__ float red[8];
    int tid = threadIdx.x;
    int i0  = blockIdx.x * 8;

    for (int v = tid; v < 8 * DIM; v += 256)
        ei[v >> 6][v & 63] = emb[i0 * DIM + v];
    if (tid < 8) eni_s[tid] = g_en[i0 + tid];

    float sum = 0.0f;
    for (int jc = 0; jc < NE; jc += 128) {
        __syncthreads();
#pragma unroll
        for (int t = 0; t < 8; t++) {
            int v  = tid + t * 256;
            int jl = v >> 4, c4 = (v & 15) << 2;
            float4 f = *reinterpret_cast<const float4*>(emb + (jc + jl) * DIM + c4);
            ej[jl][c4 + 0] = f.x; ej[jl][c4 + 1] = f.y;
            ej[jl][c4 + 2] = f.z; ej[jl][c4 + 3] = f.w;
        }
        __syncthreads();
        int il = tid >> 5, lane = tid & 31;
#pragma unroll
        for (int jj = 0; jj < 4; jj++) {
            int jl = lane + 32 * jj;
            float dot = 0.0f;
#pragma unroll 16
            for (int k = 0; k < DIM; k++)
                dot = fmaf(ei[il][k], ej[jl][k], dot);
            float d2 = eni_s[il] + g_en[jc + jl] - 2.0f * dot;
            sum += sqrtf(fmaxf(d2, 0.0f));
        }
    }
#pragma unroll
    for (int off = 16; off > 0; off >>= 1)
        sum += __shfl_down_sync(0xffffffffu, sum, off);
    if ((tid & 31) == 0) red[tid >> 5] = sum;
    __syncthreads();
    if (tid == 0) {
        float s = 0.0f;
#pragma unroll
        for (int w = 0; w < 8; w++) s += red[w];
        atomicAdd(&g_edist, (double)s);
    }
}

// ============================================================
// filter: split-bf16 MMA scoring + per-row (min1,min2).
// 256 thr = 8 warps x 2 m-tiles (32 rows) = 256 rows/CTA, grid 256.
// A staged directly from fp32 z (split in-regs, R7-validated).
// Each B ldmatrix.x4 feeds 4 MMAs (B smem wavefronts halved).
// K=192: ks 0-3 zh*eh, 4-7 zh*el, 8-11 zl*eh.
// ============================================================
__global__ __launch_bounds__(256, 2) void vq_filter(const float* __restrict__ z) {
    extern __shared__ __nv_bfloat16 sm[];
    __nv_bfloat16* As = sm;                           // [256][LDA]
    __nv_bfloat16* Bs = sm + MROWS * LDA;             // [128][LDA]
    float* en_s = (float*)(sm + (MROWS + 128) * LDA); // [128]

    const int tid = threadIdx.x, lane = tid & 31, w = tid >> 5;
    const int m0 = blockIdx.x * MROWS;

    // stage A: load z fp32 coalesced, split to bf16 (h|l) in regs
    const float4* z4 = (const float4*)(z + (size_t)m0 * DIM);
#pragma unroll
    for (int i = 0; i < 16; i++) {
        int idx = tid + i * 256;
        int r = idx >> 4, q = idx & 15;
        float4 f = z4[r * 16 + q];
        uint2 hp, lp;
        hp.x = pack_bf16_h(f.x, f.y); hp.y = pack_bf16_h(f.z, f.w);
        lp.x = pack_bf16_l(f.x, f.y); lp.y = pack_bf16_l(f.z, f.w);
        *(uint2*)(As + r * LDA + q * 4)      = hp;
        *(uint2*)(As + r * LDA + 64 + q * 4) = lp;
    }
    __syncthreads();

    // A fragments: f 0-3 = zh k0..63, f 4-7 = zl ; 2 m-tiles per warp
    unsigned afr[8][2][4];
    unsigned abase = (unsigned)__cvta_generic_to_shared(As);
    {
        int acol8 = (lane >> 4) * 8;
#pragma unroll
        for (int f = 0; f < 8; f++) {
            int aoff = (f < 4) ? 16 * f : 64 + 16 * (f - 4);
#pragma unroll
            for (int m = 0; m < 2; m++) {
                int arow = w * 32 + m * 16 + (lane & 15);
                ldmx4(afr[f][m], abase + (unsigned)(arow * LDA + aoff + acol8) * 2u);
            }
        }
    }

    // min-tracking: slot = m*2+s -> row  w*32 + m*16 + (lane>>2) + 8*s
    float m1v[4], m2v[4]; int m1i[4];
#pragma unroll
    for (int s = 0; s < 4; s++) { m1v[s] = FLT_MAX; m2v[s] = FLT_MAX; m1i[s] = 0; }

    unsigned bbase = (unsigned)__cvta_generic_to_shared(Bs);
    const uint4* esp4 = (const uint4*)g_esplit;
    const int brow_in = ((lane >> 4) << 3) + (lane & 7);
    const int bcol8   = ((lane >> 3) & 1) * 8;
    const int ccol    = 2 * (lane & 3);

    for (int ch = 0; ch < 8; ch++) {
        const int cb = ch * 128;
        __syncthreads();                              // Bs free from previous chunk
#pragma unroll
        for (int i = 0; i < 8; i++) {
            int idx = tid + i * 256;
            int r = idx >> 4, q = idx & 15;
            *(uint4*)((char*)Bs + r * (LDA * 2) + q * 16) = esp4[(cb + r) * 16 + q];
        }
        if (tid < 128) en_s[tid] = g_en[cb + tid];
        __syncthreads();

#pragma unroll 1
        for (int ntp = 0; ntp < 8; ntp++) {           // 16 codes per iter
            float acc[2][2][4];
#pragma unroll
            for (int m = 0; m < 2; m++)
#pragma unroll
                for (int g = 0; g < 2; g++)
#pragma unroll
                    for (int q = 0; q < 4; q++) acc[m][g][q] = 0.0f;

            const int brow = ntp * 16 + brow_in;
#pragma unroll
            for (int ks = 0; ks < 12; ks++) {
                int f    = (ks < 8) ? (ks & 3) : (4 + (ks & 3));
                int boff = (ks < 4) ? 16 * ks : (ks < 8) ? 64 + 16 * (ks - 4) : 16 * (ks - 8);
                unsigned bf[4];
                ldmx4(bf, bbase + (unsigned)(brow * LDA + boff + bcol8) * 2u);
                mma16816(acc[0][0], afr[f][0], bf);
                mma16816(acc[0][1], afr[f][0], bf + 2);
                mma16816(acc[1][0], afr[f][1], bf);
                mma16816(acc[1][1], afr[f][1], bf + 2);
            }
            // epilogue: per slot codes ascend: g00, g00+1, g10, g10+1
            int l0 = ntp * 16 + ccol;
            float en00 = en_s[l0],     en01 = en_s[l0 + 1];
            float en10 = en_s[l0 + 8], en11 = en_s[l0 + 9];
            int g00 = cb + l0, g10 = g00 + 8;
#pragma unroll
            for (int m = 0; m < 2; m++)
#pragma unroll
            for (int s = 0; s < 2; s++) {
                int sl = m * 2 + s;
                float u0 = fmaf(-2.0f, acc[m][0][2 * s],     en00);
                float u1 = fmaf(-2.0f, acc[m][0][2 * s + 1], en01);
                float u2 = fmaf(-2.0f, acc[m][1][2 * s],     en10);
                float u3 = fmaf(-2.0f, acc[m][1][2 * s + 1], en11);
                if (u0 < m1v[sl]) { m2v[sl] = m1v[sl]; m1v[sl] = u0; m1i[sl] = g00; }
                else if (u0 < m2v[sl]) m2v[sl] = u0;
                if (u1 < m1v[sl]) { m2v[sl] = m1v[sl]; m1v[sl] = u1; m1i[sl] = g00 + 1; }
                else if (u1 < m2v[sl]) m2v[sl] = u1;
                if (u2 < m1v[sl]) { m2v[sl] = m1v[sl]; m1v[sl] = u2; m1i[sl] = g10; }
                else if (u2 < m2v[sl]) m2v[sl] = u2;
                if (u3 < m1v[sl]) { m2v[sl] = m1v[sl]; m1v[sl] = u3; m1i[sl] = g10 + 1; }
                else if (u3 < m2v[sl]) m2v[sl] = u3;
            }
        }
    }

    // quad reduce (cols live in lanes xor 1,2); lexicographic (val, idx)
#pragma unroll
    for (int off = 1; off <= 2; off <<= 1) {
#pragma unroll
        for (int s = 0; s < 4; s++) {
            float ov = __shfl_xor_sync(0xffffffffu, m1v[s], off);
            int   oi = __shfl_xor_sync(0xffffffffu, m1i[s], off);
            float o2 = __shfl_xor_sync(0xffffffffu, m2v[s], off);
            float nm2 = fminf(fmaxf(m1v[s], ov), fminf(m2v[s], o2));
            if (ov < m1v[s] || (ov == m1v[s] && oi < m1i[s])) { m1v[s] = ov; m1i[s] = oi; }
            m2v[s] = nm2;
        }
    }
    if ((lane & 3) == 0) {
#pragma unroll
        for (int m = 0; m < 2; m++)
#pragma unroll
        for (int s = 0; s < 2; s++) {
            int sl = m * 2 + s;
            int grow = m0 + w * 32 + m * 16 + (lane >> 2) + 8 * s;
            g_idx[grow] = m1i[sl];
            if (m2v[sl] - m1v[sl] < DELTA) {
                int p = atomicAdd(&g_amb_cnt, 1);
                g_amb_rows[p] = grow;
            }
        }
    }
}

// ============================================================
// rescan (tiled, R10-validated): EXACT reference arithmetic over
// the compacted ambiguous-row list. zsq computed locally.
//   d = fl( fl(zsq + en) - 2*dot ),  dot = seq ascending-k fmaf.
// ============================================================
#define MT  128
#define LDZ 65
__global__ __launch_bounds__(256) void vq_rescan(const float* __restrict__ z,
                                                 const float* __restrict__ emb) {
    extern __shared__ float smf[];
    float (*zs)[LDZ] = (float(*)[LDZ])smf;
    float (*es)[LDZ] = (float(*)[LDZ])(smf + MT * LDZ);
    float* szs = smf + 2 * MT * LDZ;               // [MT]
    int*   rows = (int*)(szs + MT);                // [MT]

    const int tid = threadIdx.x;
    const int tx  = tid & 15, ty = tid >> 4;
    const int cnt = g_amb_cnt;
    const int ntiles = (cnt + MT - 1) >> 7;

    for (int tile = blockIdx.x; tile < ntiles; tile += gridDim.x) {
        if (tid < MT) {
            int a = tile * MT + tid;
            rows[tid] = g_amb_rows[a < cnt ? a : cnt - 1];
        }
        __syncthreads();
#pragma unroll
        for (int t = 0; t < 8; t++) {
            int v = tid + t * 256;
            int r = v >> 4, c4 = (v & 15) << 2;
            float4 f = *reinterpret_cast<const float4*>(z + (size_t)rows[r] * DIM + c4);
            zs[r][c4 + 0] = f.x; zs[r][c4 + 1] = f.y;
            zs[r][c4 + 2] = f.z; zs[r][c4 + 3] = f.w;
        }
        __syncthreads();
        if (tid < MT) {
            float s = 0.0f;
#pragma unroll
            for (int k = 0; k < DIM; k++) {
                float sq = __fmul_rn(zs[tid][k], zs[tid][k]);
                s = __fadd_rn(s, sq);
            }
            szs[tid] = s;
        }
        __syncthreads();

        float Srow[8];
#pragma unroll
        for (int i = 0; i < 8; i++) Srow[i] = szs[ty + 16 * i];

        float minv[8]; int mini[8];
#pragma unroll
        for (int i = 0; i < 8; i++) { minv[i] = 3.4e38f; mini[i] = 0; }

        for (int n0 = 0; n0 < NE; n0 += 128) {
            __syncthreads();
#pragma unroll
            for (int t = 0; t < 8; t++) {
                int v = tid + t * 256;
                int cl = v >> 4, c4 = (v & 15) << 2;
                float4 f = *reinterpret_cast<const float4*>(emb + (n0 + cl) * DIM + c4);
                es[cl][c4 + 0] = f.x; es[cl][c4 + 1] = f.y;
                es[cl][c4 + 2] = f.z; es[cl][c4 + 3] = f.w;
            }
            __syncthreads();

            float dot[8][8];
#pragma unroll
            for (int i = 0; i < 8; i++)
#pragma unroll
                for (int j = 0; j < 8; j++) dot[i][j] = 0.0f;
#pragma unroll 8
            for (int k = 0; k < DIM; k++) {
                float a[8], b[8];
#pragma unroll
                for (int i = 0; i < 8; i++) a[i] = zs[ty + 16 * i][k];
#pragma unroll
                for (int j = 0; j < 8; j++) b[j] = es[tx + 16 * j][k];
#pragma unroll
                for (int i = 0; i < 8; i++)
#pragma unroll
                    for (int j = 0; j < 8; j++)
                        dot[i][j] = fmaf(a[i], b[j], dot[i][j]);
            }
#pragma unroll
            for (int j = 0; j < 8; j++) {
                int code = n0 + tx + 16 * j;
                float en = __ldg(&g_en[code]);
#pragma unroll
                for (int i = 0; i < 8; i++) {
                    float t = __fadd_rn(Srow[i], en);
                    float s = __fadd_rn(t, -2.0f * dot[i][j]);
                    if (s < minv[i]) { minv[i] = s; mini[i] = code; }
                }
            }
        }
#pragma unroll
        for (int off = 8; off > 0; off >>= 1) {
#pragma unroll
            for (int i = 0; i < 8; i++) {
                float ov = __shfl_down_sync(0xffffffffu, minv[i], off, 16);
                int   oi = __shfl_down_sync(0xffffffffu, mini[i], off, 16);
                if (ov < minv[i] || (ov == minv[i] && oi < mini[i])) {
                    minv[i] = ov; mini[i] = oi;
                }
            }
        }
        if (tx == 0) {
#pragma unroll
            for (int i = 0; i < 8; i++) {
                int sl = ty + 16 * i;
                if (tile * MT + sl < cnt) g_idx[rows[sl]] = mini[i];
            }
        }
        __syncthreads();
    }
}

// ============================================================
// emit: gather z_q, indices, histogram, mse (coalesced).
// ============================================================
__global__ __launch_bounds__(256) void vq_emit(const float* __restrict__ z,
                                               const float* __restrict__ emb,
                                               float* __restrict__ out) {
    __shared__ float red[8];
    int tid = threadIdx.x;
    int m0  = blockIdx.x * 128;
    float* zq   = out + ZQ_OFF;
    float* oidx = out + IDX_OFF;
    int col = tid & 63, r0 = tid >> 6;

    float lsum = 0.0f;
#pragma unroll 4
    for (int it = 0; it < 32; ++it) {
        int r   = m0 + r0 + 4 * it;
        int gi  = r * DIM + col;
        int idx = g_idx[r];
        float q  = emb[idx * DIM + col];
        float zv = z[gi];
        zq[gi] = q;
        float d = q - zv;
        lsum = fmaf(d, d, lsum);
        if (col == 0) {
            oidx[r] = (float)idx;
            atomicAdd(&g_counts[idx], 1.0f);
        }
    }
#pragma unroll
    for (int off = 16; off > 0; off >>= 1)
        lsum += __shfl_down_sync(0xffffffffu, lsum, off);
    if ((tid & 31) == 0) red[tid >> 5] = lsum;
    __syncthreads();
    if (tid == 0) {
        float s = 0.0f;
#pragma unroll
        for (int w = 0; w < 8; w++) s += red[w];
        atomicAdd(&g_mse, (double)s);
    }
}

// ============================================================
// finalize: perplexity + loss scalars (validated).
// ============================================================
__global__ void vq_finalize(float* __restrict__ out) {
    __shared__ float red[32];
    int tid = threadIdx.x;
    float p = g_counts[tid] * (1.0f / (float)NROWS);
    float h = -p * logf(p + 1e-10f);
#pragma unroll
    for (int off = 16; off > 0; off >>= 1)
        h += __shfl_down_sync(0xffffffffu, h, off);
    if ((tid & 31) == 0) red[tid >> 5] = h;
    __syncthreads();
    if (tid == 0) {
        float H = 0.0f;
#pragma unroll
        for (int w = 0; w < 32; w++) H += red[w];
        float perp = expf(H);
        double mse = g_mse / (double)(NROWS * DIM);
        double mean_tril = (g_edist * 0.5) / ((double)NE * (double)NE);
        double e_loss = exp(-mean_tril / 0.1);
        out[0]        = (float)(1.25 * mse + e_loss);
        out[PERP_OFF] = perp;
    }
}

// ============================================================
extern "C" void kernel_launch(void* const* d_in, const int* in_sizes, int n_in,
                              void* d_out, int out_size) {
    const float* z   = (const float*)d_in[0];
    const float* emb = (const float*)d_in[1];
    float* out = (float*)d_out;

    const int fsmem = (MROWS + 128) * LDA * 2 + 128 * 4;   // 104,960 B
    cudaFuncSetAttribute(vq_filter, cudaFuncAttributeMaxDynamicSharedMemorySize, fsmem);
    const int rsmem = (2 * MT * LDZ + MT) * (int)sizeof(float) + MT * (int)sizeof(int);
    cudaFuncSetAttribute(vq_rescan, cudaFuncAttributeMaxDynamicSharedMemorySize, rsmem);

    // fork/join so vq_pairs overlaps the filter chain under graph capture
    cudaStream_t s2;
    cudaStreamCreateWithFlags(&s2, cudaStreamNonBlocking);
    cudaEvent_t eFork, eJoin;
    cudaEventCreateWithFlags(&eFork, cudaEventDisableTiming);
    cudaEventCreateWithFlags(&eJoin, cudaEventDisableTiming);

    vq_init<<<NE / 64, 256>>>(emb);
    cudaEventRecord(eFork, 0);
    cudaStreamWaitEvent(s2, eFork, 0);
    vq_pairs<<<NE / 8, 256, 0, s2>>>(emb);          // side stream
    cudaEventRecord(eJoin, s2);

    vq_filter<<<NROWS / MROWS, 256, fsmem>>>(z);    // main stream
    vq_rescan<<<64, 256, rsmem>>>(z, emb);
    vq_emit<<<NROWS / 128, 256>>>(z, emb, out);
    cudaStreamWaitEvent(0, eJoin, 0);               // join pairs before finalize
    vq_finalize<<<1, 1024>>>(out);

    cudaEventDestroy(eFork);
    cudaEventDestroy(eJoin);
    cudaStreamDestroy(s2);
}

// round 13
// speedup vs baseline: 2.0690x; 1.3833x over previous
#include <cuda_runtime.h>
#include <cuda_bf16.h>
#include <math.h>
#include <float.h>

#define NROWS 65536      // 32*32*64
#define DIM   64
#define NE    1024
#define LDE   65         // vq_pairs tile ld

// Output layout (float32, return-order flatten)
#define ZQ_OFF   1
#define PERP_OFF (1 + NROWS*DIM)
#define IDX_OFF  (2 + NROWS*DIM)

#define DELTA 4e-5f      // ambiguity margin (validated R5-R11)
#define LDA   136        // padded split-row ld in bf16 (272B = 17*16B)
#define MROWS 256        // rows per filter CTA (2 m-tiles per warp)

// ---- scratch (no allocations allowed) ----
__device__ float  g_counts[NE];
__device__ float  g_en[NE];
__device__ int    g_idx[NROWS];
__device__ int    g_amb_rows[NROWS];
__device__ unsigned long long g_amb_key[NROWS];
__device__ int    g_amb_cnt;
__device__ double g_mse;
__device__ double g_edist;
__device__ __nv_bfloat16 g_esplit[NE * 128];       // [code][ eh(64) | el(64) ]

// ============================================================
// PTX helpers (fragment layouts validated bitwise R5/R6/R7/R11)
// ============================================================
__device__ __forceinline__ void ldmx4(unsigned* r, unsigned addr) {
    asm volatile("ldmatrix.sync.aligned.m8n8.x4.shared.b16 {%0,%1,%2,%3}, [%4];"
                 : "=r"(r[0]), "=r"(r[1]), "=r"(r[2]), "=r"(r[3]) : "r"(addr));
}
__device__ __forceinline__ void mma16816(float* c, const unsigned* a, const unsigned* b) {
    asm volatile("mma.sync.aligned.m16n8k16.row.col.f32.bf16.bf16.f32 "
                 "{%0,%1,%2,%3}, {%4,%5,%6,%7}, {%8,%9}, {%0,%1,%2,%3};"
                 : "+f"(c[0]), "+f"(c[1]), "+f"(c[2]), "+f"(c[3])
                 : "r"(a[0]), "r"(a[1]), "r"(a[2]), "r"(a[3]), "r"(b[0]), "r"(b[1]));
}
__device__ __forceinline__ unsigned pack_bf16_h(float x, float y) {
    __nv_bfloat16 hx = __float2bfloat16(x), hy = __float2bfloat16(y);
    return (unsigned)__bfloat16_as_ushort(hx) | ((unsigned)__bfloat16_as_ushort(hy) << 16);
}
__device__ __forceinline__ unsigned pack_bf16_l(float x, float y) {
    __nv_bfloat16 hx = __float2bfloat16(x), hy = __float2bfloat16(y);
    __nv_bfloat16 lx = __float2bfloat16(x - __bfloat162float(hx));
    __nv_bfloat16 ly = __float2bfloat16(y - __bfloat162float(hy));
    return (unsigned)__bfloat16_as_ushort(lx) | ((unsigned)__bfloat16_as_ushort(ly) << 16);
}
// order-preserving float -> uint (injective; total order matches float <)
__device__ __forceinline__ unsigned ford(float f) {
    unsigned u = __float_as_uint(f);
    return (u & 0x80000000u) ? ~u : (u | 0x80000000u);
}

// ============================================================
// init: coalesced. exact ||e||^2 (sequential UNFUSED) + bf16
// split of the codebook + zero accumulators.
// ============================================================
__global__ __launch_bounds__(256) void vq_init(const float* __restrict__ emb) {
    __shared__ float es[64][65];
    int tid = threadIdx.x;
    int c0  = blockIdx.x * 64;
#pragma unroll
    for (int i = 0; i < 16; i++) {
        int idx = tid + i * 256;
        int r = idx >> 6, c = idx & 63;
        es[r][c] = emb[(c0 + r) * DIM + c];
    }
    if (blockIdx.x == 0) {
#pragma unroll
        for (int q = 0; q < 4; q++) g_counts[tid + q * 256] = 0.0f;
        if (tid == 0) { g_mse = 0.0; g_edist = 0.0; g_amb_cnt = 0; }
    }
    __syncthreads();
    if (tid < 64) {
        float s = 0.0f;
#pragma unroll
        for (int k = 0; k < DIM; k++) {
            float sq = __fmul_rn(es[tid][k], es[tid][k]);
            s = __fadd_rn(s, sq);
        }
        g_en[c0 + tid] = s;
    }
#pragma unroll
    for (int i = 0; i < 16; i++) {
        int idx = tid + i * 256;
        int r = idx >> 6, c = idx & 63;
        float v = es[r][c];
        __nv_bfloat16 h = __float2bfloat16(v);
        __nv_bfloat16 l = __float2bfloat16(v - __bfloat162float(h));
        g_esplit[(c0 + r) * 128 + c]      = h;
        g_esplit[(c0 + r) * 128 + 64 + c] = l;
    }
}

// ============================================================
// codebook pairwise distances (e_loss) — unchanged, validated.
// Runs on a forked stream, overlapped with vq_filter.
// ============================================================
__global__ __launch_bounds__(256) void vq_pairs(const float* __restrict__ emb) {
    __shared__ float ei[8][DIM];
    __shared__ float ej[128][LDE];
    __shared__ float eni_s[8];
    __shared__ float red[8];
    int tid = threadIdx.x;
    int i0  = blockIdx.x * 8;

    for (int v = tid; v < 8 * DIM; v += 256)
        ei[v >> 6][v & 63] = emb[i0 * DIM + v];
    if (tid < 8) eni_s[tid] = g_en[i0 + tid];

    float sum = 0.0f;
    for (int jc = 0; jc < NE; jc += 128) {
        __syncthreads();
#pragma unroll
        for (int t = 0; t < 8; t++) {
            int v  = tid + t * 256;
            int jl = v >> 4, c4 = (v & 15) << 2;
            float4 f = *reinterpret_cast<const float4*>(emb + (jc + jl) * DIM + c4);
            ej[jl][c4 + 0] = f.x; ej[jl][c4 + 1] = f.y;
            ej[jl][c4 + 2] = f.z; ej[jl][c4 + 3] = f.w;
        }
        __syncthreads();
        int il = tid >> 5, lane = tid & 31;
#pragma unroll
        for (int jj = 0; jj < 4; jj++) {
            int jl = lane + 32 * jj;
            float dot = 0.0f;
#pragma unroll 16
            for (int k = 0; k < DIM; k++)
                dot = fmaf(ei[il][k], ej[jl][k], dot);
            float d2 = eni_s[il] + g_en[jc + jl] - 2.0f * dot;
            sum += sqrtf(fmaxf(d2, 0.0f));
        }
    }
#pragma unroll
    for (int off = 16; off > 0; off >>= 1)
        sum += __shfl_down_sync(0xffffffffu, sum, off);
    if ((tid & 31) == 0) red[tid >> 5] = sum;
    __syncthreads();
    if (tid == 0) {
        float s = 0.0f;
#pragma unroll
        for (int w = 0; w < 8; w++) s += red[w];
        atomicAdd(&g_edist, (double)s);
    }
}

// ============================================================
// filter (R11-validated): split-bf16 MMA scoring + (min1,min2).
// 256 thr = 8 warps x 2 m-tiles (32 rows) = 256 rows/CTA.
// ============================================================
__global__ __launch_bounds__(256, 2) void vq_filter(const float* __restrict__ z) {
    extern __shared__ __nv_bfloat16 sm[];
    __nv_bfloat16* As = sm;                           // [256][LDA]
    __nv_bfloat16* Bs = sm + MROWS * LDA;             // [128][LDA]
    float* en_s = (float*)(sm + (MROWS + 128) * LDA); // [128]

    const int tid = threadIdx.x, lane = tid & 31, w = tid >> 5;
    const int m0 = blockIdx.x * MROWS;

    const float4* z4 = (const float4*)(z + (size_t)m0 * DIM);
#pragma unroll
    for (int i = 0; i < 16; i++) {
        int idx = tid + i * 256;
        int r = idx >> 4, q = idx & 15;
        float4 f = z4[r * 16 + q];
        uint2 hp, lp;
        hp.x = pack_bf16_h(f.x, f.y); hp.y = pack_bf16_h(f.z, f.w);
        lp.x = pack_bf16_l(f.x, f.y); lp.y = pack_bf16_l(f.z, f.w);
        *(uint2*)(As + r * LDA + q * 4)      = hp;
        *(uint2*)(As + r * LDA + 64 + q * 4) = lp;
    }
    __syncthreads();

    unsigned afr[8][2][4];
    unsigned abase = (unsigned)__cvta_generic_to_shared(As);
    {
        int acol8 = (lane >> 4) * 8;
#pragma unroll
        for (int f = 0; f < 8; f++) {
            int aoff = (f < 4) ? 16 * f : 64 + 16 * (f - 4);
#pragma unroll
            for (int m = 0; m < 2; m++) {
                int arow = w * 32 + m * 16 + (lane & 15);
                ldmx4(afr[f][m], abase + (unsigned)(arow * LDA + aoff + acol8) * 2u);
            }
        }
    }

    float m1v[4], m2v[4]; int m1i[4];
#pragma unroll
    for (int s = 0; s < 4; s++) { m1v[s] = FLT_MAX; m2v[s] = FLT_MAX; m1i[s] = 0; }

    unsigned bbase = (unsigned)__cvta_generic_to_shared(Bs);
    const uint4* esp4 = (const uint4*)g_esplit;
    const int brow_in = ((lane >> 4) << 3) + (lane & 7);
    const int bcol8   = ((lane >> 3) & 1) * 8;
    const int ccol    = 2 * (lane & 3);

    for (int ch = 0; ch < 8; ch++) {
        const int cb = ch * 128;
        __syncthreads();
#pragma unroll
        for (int i = 0; i < 8; i++) {
            int idx = tid + i * 256;
            int r = idx >> 4, q = idx & 15;
            *(uint4*)((char*)Bs + r * (LDA * 2) + q * 16) = esp4[(cb + r) * 16 + q];
        }
        if (tid < 128) en_s[tid] = g_en[cb + tid];
        __syncthreads();

#pragma unroll 1
        for (int ntp = 0; ntp < 8; ntp++) {
            float acc[2][2][4];
#pragma unroll
            for (int m = 0; m < 2; m++)
#pragma unroll
                for (int g = 0; g < 2; g++)
#pragma unroll
                    for (int q = 0; q < 4; q++) acc[m][g][q] = 0.0f;

            const int brow = ntp * 16 + brow_in;
#pragma unroll
            for (int ks = 0; ks < 12; ks++) {
                int f    = (ks < 8) ? (ks & 3) : (4 + (ks & 3));
                int boff = (ks < 4) ? 16 * ks : (ks < 8) ? 64 + 16 * (ks - 4) : 16 * (ks - 8);
                unsigned bf[4];
                ldmx4(bf, bbase + (unsigned)(brow * LDA + boff + bcol8) * 2u);
                mma16816(acc[0][0], afr[f][0], bf);
                mma16816(acc[0][1], afr[f][0], bf + 2);
                mma16816(acc[1][0], afr[f][1], bf);
                mma16816(acc[1][1], afr[f][1], bf + 2);
            }
            int l0 = ntp * 16 + ccol;
            float en00 = en_s[l0],     en01 = en_s[l0 + 1];
            float en10 = en_s[l0 + 8], en11 = en_s[l0 + 9];
            int g00 = cb + l0, g10 = g00 + 8;
#pragma unroll
            for (int m = 0; m < 2; m++)
#pragma unroll
            for (int s = 0; s < 2; s++) {
                int sl = m * 2 + s;
                float u0 = fmaf(-2.0f, acc[m][0][2 * s],     en00);
                float u1 = fmaf(-2.0f, acc[m][0][2 * s + 1], en01);
                float u2 = fmaf(-2.0f, acc[m][1][2 * s],     en10);
                float u3 = fmaf(-2.0f, acc[m][1][2 * s + 1], en11);
                if (u0 < m1v[sl]) { m2v[sl] = m1v[sl]; m1v[sl] = u0; m1i[sl] = g00; }
                else if (u0 < m2v[sl]) m2v[sl] = u0;
                if (u1 < m1v[sl]) { m2v[sl] = m1v[sl]; m1v[sl] = u1; m1i[sl] = g00 + 1; }
                else if (u1 < m2v[sl]) m2v[sl] = u1;
                if (u2 < m1v[sl]) { m2v[sl] = m1v[sl]; m1v[sl] = u2; m1i[sl] = g10; }
                else if (u2 < m2v[sl]) m2v[sl] = u2;
                if (u3 < m1v[sl]) { m2v[sl] = m1v[sl]; m1v[sl] = u3; m1i[sl] = g10 + 1; }
                else if (u3 < m2v[sl]) m2v[sl] = u3;
            }
        }
    }

#pragma unroll
    for (int off = 1; off <= 2; off <<= 1) {
#pragma unroll
        for (int s = 0; s < 4; s++) {
            float ov = __shfl_xor_sync(0xffffffffu, m1v[s], off);
            int   oi = __shfl_xor_sync(0xffffffffu, m1i[s], off);
            float o2 = __shfl_xor_sync(0xffffffffu, m2v[s], off);
            float nm2 = fminf(fmaxf(m1v[s], ov), fminf(m2v[s], o2));
            if (ov < m1v[s] || (ov == m1v[s] && oi < m1i[s])) { m1v[s] = ov; m1i[s] = oi; }
            m2v[s] = nm2;
        }
    }
    if ((lane & 3) == 0) {
#pragma unroll
        for (int m = 0; m < 2; m++)
#pragma unroll
        for (int s = 0; s < 2; s++) {
            int sl = m * 2 + s;
            int grow = m0 + w * 32 + m * 16 + (lane >> 2) + 8 * s;
            g_idx[grow] = m1i[sl];
            if (m2v[sl] - m1v[sl] < DELTA) {
                int p = atomicAdd(&g_amb_cnt, 1);
                g_amb_rows[p] = grow;
                g_amb_key[p]  = 0xFFFFFFFFFFFFFFFFull;   // init merge key
            }
        }
    }
}

// ============================================================
// rescan v5: EXACT reference arithmetic; work item = (tile of
// 128 amb rows) x (128-code segment) -> 8x more parallel CTAs.
// Cross-segment merge: atomicMin on packed (ford(d)<<32 | code)
// == lexicographic (value, lowest code) min, exact semantics.
// ============================================================
#define MT  128
#define LDZ 65
__global__ __launch_bounds__(256) void vq_rescan(const float* __restrict__ z,
                                                 const float* __restrict__ emb) {
    extern __shared__ float smf[];
    float (*zs)[LDZ] = (float(*)[LDZ])smf;
    float (*es)[LDZ] = (float(*)[LDZ])(smf + MT * LDZ);
    float* szs = smf + 2 * MT * LDZ;               // [MT]
    int*   rows = (int*)(szs + MT);                // [MT]

    const int tid = threadIdx.x;
    const int tx  = tid & 15, ty = tid >> 4;
    const int cnt = g_amb_cnt;
    const int nwork = ((cnt + MT - 1) >> 7) << 3;  // ntiles * 8 segments

    for (int wk = blockIdx.x; wk < nwork; wk += gridDim.x) {
        const int tile = wk >> 3;
        const int n0   = (wk & 7) * 128;

        if (tid < MT) {
            int a = tile * MT + tid;
            rows[tid] = g_amb_rows[a < cnt ? a : cnt - 1];
        }
        __syncthreads();
#pragma unroll
        for (int t = 0; t < 8; t++) {
            int v = tid + t * 256;
            int r = v >> 4, c4 = (v & 15) << 2;
            float4 f = *reinterpret_cast<const float4*>(z + (size_t)rows[r] * DIM + c4);
            zs[r][c4 + 0] = f.x; zs[r][c4 + 1] = f.y;
            zs[r][c4 + 2] = f.z; zs[r][c4 + 3] = f.w;
        }
        // emb segment [n0, n0+128)
#pragma unroll
        for (int t = 0; t < 8; t++) {
            int v = tid + t * 256;
            int cl = v >> 4, c4 = (v & 15) << 2;
            float4 f = *reinterpret_cast<const float4*>(emb + (n0 + cl) * DIM + c4);
            es[cl][c4 + 0] = f.x; es[cl][c4 + 1] = f.y;
            es[cl][c4 + 2] = f.z; es[cl][c4 + 3] = f.w;
        }
        __syncthreads();
        if (tid < MT) {                             // exact unfused zsq
            float s = 0.0f;
#pragma unroll
            for (int k = 0; k < DIM; k++) {
                float sq = __fmul_rn(zs[tid][k], zs[tid][k]);
                s = __fadd_rn(s, sq);
            }
            szs[tid] = s;
        }
        __syncthreads();

        float Srow[8];
#pragma unroll
        for (int i = 0; i < 8; i++) Srow[i] = szs[ty + 16 * i];

        float minv[8]; int mini[8];
#pragma unroll
        for (int i = 0; i < 8; i++) { minv[i] = 3.4e38f; mini[i] = 0; }

        float dot[8][8];
#pragma unroll
        for (int i = 0; i < 8; i++)
#pragma unroll
            for (int j = 0; j < 8; j++) dot[i][j] = 0.0f;
#pragma unroll 8
        for (int k = 0; k < DIM; k++) {
            float a[8], b[8];
#pragma unroll
            for (int i = 0; i < 8; i++) a[i] = zs[ty + 16 * i][k];
#pragma unroll
            for (int j = 0; j < 8; j++) b[j] = es[tx + 16 * j][k];
#pragma unroll
            for (int i = 0; i < 8; i++)
#pragma unroll
                for (int j = 0; j < 8; j++)
                    dot[i][j] = fmaf(a[i], b[j], dot[i][j]);   // seq ascending k
        }
#pragma unroll
        for (int j = 0; j < 8; j++) {
            int code = n0 + tx + 16 * j;            // ascending per thread
            float en = __ldg(&g_en[code]);
#pragma unroll
            for (int i = 0; i < 8; i++) {
                float t = __fadd_rn(Srow[i], en);
                float s = __fadd_rn(t, -2.0f * dot[i][j]);
                if (s < minv[i]) { minv[i] = s; mini[i] = code; }
            }
        }
#pragma unroll
        for (int off = 8; off > 0; off >>= 1) {
#pragma unroll
            for (int i = 0; i < 8; i++) {
                float ov = __shfl_down_sync(0xffffffffu, minv[i], off, 16);
                int   oi = __shfl_down_sync(0xffffffffu, mini[i], off, 16);
                if (ov < minv[i] || (ov == minv[i] && oi < mini[i])) {
                    minv[i] = ov; mini[i] = oi;
                }
            }
        }
        if (tx == 0) {
#pragma unroll
            for (int i = 0; i < 8; i++) {
                int sl = ty + 16 * i;
                int a  = tile * MT + sl;
                unsigned long long key =
                    ((unsigned long long)ford(minv[i]) << 32) | (unsigned)mini[i];
                atomicMin(&g_amb_key[a], key);      // a<cnt read later; a>=cnt inert
            }
        }
        __syncthreads();
    }
}

// ============================================================
// fix: unpack merged keys into g_idx for flagged rows.
// ============================================================
__global__ void vq_fix(void) {
    int cnt = g_amb_cnt;
    for (int a = blockIdx.x * blockDim.x + threadIdx.x; a < cnt;
         a += gridDim.x * blockDim.x)
        g_idx[g_amb_rows[a]] = (int)(unsigned)(g_amb_key[a] & 0xFFFFFFFFull);
}

// ============================================================
// emit: gather z_q, indices, histogram, mse (coalesced).
// ============================================================
__global__ __launch_bounds__(256) void vq_emit(const float* __restrict__ z,
                                               const float* __restrict__ emb,
                                               float* __restrict__ out) {
    __shared__ float red[8];
    int tid = threadIdx.x;
    int m0  = blockIdx.x * 128;
    float* zq   = out + ZQ_OFF;
    float* oidx = out + IDX_OFF;
    int col = tid & 63, r0 = tid >> 6;

    float lsum = 0.0f;
#pragma unroll 4
    for (int it = 0; it < 32; ++it) {
        int r   = m0 + r0 + 4 * it;
        int gi  = r * DIM + col;
        int idx = g_idx[r];
        float q  = emb[idx * DIM + col];
        float zv = z[gi];
        zq[gi] = q;
        float d = q - zv;
        lsum = fmaf(d, d, lsum);
        if (col == 0) {
            oidx[r] = (float)idx;
            atomicAdd(&g_counts[idx], 1.0f);
        }
    }
#pragma unroll
    for (int off = 16; off > 0; off >>= 1)
        lsum += __shfl_down_sync(0xffffffffu, lsum, off);
    if ((tid & 31) == 0) red[tid >> 5] = lsum;
    __syncthreads();
    if (tid == 0) {
        float s = 0.0f;
#pragma unroll
        for (int w = 0; w < 8; w++) s += red[w];
        atomicAdd(&g_mse, (double)s);
    }
}

// ============================================================
// finalize: perplexity + loss scalars (validated).
// ============================================================
__global__ void vq_finalize(float* __restrict__ out) {
    __shared__ float red[32];
    int tid = threadIdx.x;
    float p = g_counts[tid] * (1.0f / (float)NROWS);
    float h = -p * logf(p + 1e-10f);
#pragma unroll
    for (int off = 16; off > 0; off >>= 1)
        h += __shfl_down_sync(0xffffffffu, h, off);
    if ((tid & 31) == 0) red[tid >> 5] = h;
    __syncthreads();
    if (tid == 0) {
        float H = 0.0f;
#pragma unroll
        for (int w = 0; w < 32; w++) H += red[w];
        float perp = expf(H);
        double mse = g_mse / (double)(NROWS * DIM);
        double mean_tril = (g_edist * 0.5) / ((double)NE * (double)NE);
        double e_loss = exp(-mean_tril / 0.1);
        out[0]        = (float)(1.25 * mse + e_loss);
        out[PERP_OFF] = perp;
    }
}

// ============================================================
extern "C" void kernel_launch(void* const* d_in, const int* in_sizes, int n_in,
                              void* d_out, int out_size) {
    const float* z   = (const float*)d_in[0];
    const float* emb = (const float*)d_in[1];
    float* out = (float*)d_out;

    const int fsmem = (MROWS + 128) * LDA * 2 + 128 * 4;   // 104,960 B
    cudaFuncSetAttribute(vq_filter, cudaFuncAttributeMaxDynamicSharedMemorySize, fsmem);
    const int rsmem = (2 * MT * LDZ + MT) * (int)sizeof(float) + MT * (int)sizeof(int);
    cudaFuncSetAttribute(vq_rescan, cudaFuncAttributeMaxDynamicSharedMemorySize, rsmem);

    // fork/join so vq_pairs overlaps the filter chain under graph capture
    cudaStream_t s2;
    cudaStreamCreateWithFlags(&s2, cudaStreamNonBlocking);
    cudaEvent_t eFork, eJoin;
    cudaEventCreateWithFlags(&eFork, cudaEventDisableTiming);
    cudaEventCreateWithFlags(&eJoin, cudaEventDisableTiming);

    vq_init<<<NE / 64, 256>>>(emb);
    cudaEventRecord(eFork, 0);
    cudaStreamWaitEvent(s2, eFork, 0);
    vq_pairs<<<NE / 8, 256, 0, s2>>>(emb);          // side stream
    cudaEventRecord(eJoin, s2);

    vq_filter<<<NROWS / MROWS, 256, fsmem>>>(z);    // main stream
    vq_rescan<<<128, 256, rsmem>>>(z, emb);
    vq_fix<<<16, 256>>>();
    vq_emit<<<NROWS / 128, 256>>>(z, emb, out);
    cudaStreamWaitEvent(0, eJoin, 0);               // join pairs before finalize
    vq_finalize<<<1, 1024>>>(out);

    cudaEventDestroy(eFork);
    cudaEventDestroy(eJoin);
    cudaStreamDestroy(s2);
}